// round 5
// baseline (speedup 1.0000x reference)
#include <cuda_runtime.h>

#define B_   4
#define N_   16384
#define M_   4096
#define K_   16
#define R2   0.25f
#define NQ   (B_ * M_)
#define BINS 256

// Scratch (device globals; no allocation allowed)
__device__ float4       g_pts[B_ * N_];    // (x,y,z,|p|^2)
__device__ unsigned int g_qctr;            // work queue head
__device__ int          g_hist[B_ * BINS];
__device__ int          g_off[B_ * BINS];
__device__ int          g_bin[NQ];
__device__ int          g_order[NQ];

// ---------------- prep: pts precompute + counter/hist reset ----------------
__global__ __launch_bounds__(256) void prep_kernel(const float* __restrict__ xyz) {
    int i = blockIdx.x * blockDim.x + threadIdx.x;
    if (i == 0) g_qctr = 0;
    if (i < B_ * BINS) g_hist[i] = 0;
    if (i < B_ * N_) {
        float x = xyz[3 * i + 0];
        float y = xyz[3 * i + 1];
        float z = xyz[3 * i + 2];
        // match jnp.sum(x**2,-1): (x*x + y*y) + z*z, no fma contraction
        float sq = __fadd_rn(__fadd_rn(__fmul_rn(x, x), __fmul_rn(y, y)), __fmul_rn(z, z));
        g_pts[i] = make_float4(x, y, z, sq);
    }
}

// ---------------- key: bin by descending |q|^2 (longest scan first) --------
__global__ __launch_bounds__(256) void key_kernel(const int* __restrict__ fps_idx) {
    int qid = blockIdx.x * blockDim.x + threadIdx.x;
    if (qid >= NQ) return;
    int b  = qid >> 12;
    int qi = fps_idx[qid];
    float k = g_pts[(size_t)b * N_ + qi].w;
    int bin = (int)(k * 16.0f);
    if (bin > 255) bin = 255;
    bin = 255 - bin;                 // bin 0 = largest |q|^2 = longest scan
    g_bin[qid] = bin;
    atomicAdd(&g_hist[b * BINS + bin], 1);
}

// ---------------- prefix: exclusive scan of 1024 bins (1 block) ------------
__global__ __launch_bounds__(1024) void prefix_kernel() {
    __shared__ int s[B_ * BINS];
    int t = threadIdx.x;
    int h = g_hist[t];
    s[t] = h;
    __syncthreads();
    for (int d = 1; d < B_ * BINS; d <<= 1) {
        int v = (t >= d) ? s[t - d] : 0;
        __syncthreads();
        s[t] += v;
        __syncthreads();
    }
    g_off[t] = s[t] - h;             // exclusive
}

// ---------------- scatter: build execution order ---------------------------
__global__ __launch_bounds__(256) void scatter_kernel() {
    int qid = blockIdx.x * blockDim.x + threadIdx.x;
    if (qid >= NQ) return;
    int b   = qid >> 12;
    int pos = atomicAdd(&g_off[b * BINS + g_bin[qid]], 1);
    g_order[pos] = qid;
}

// DO NOT change: reproduces reference's expanded |q|^2+|p|^2-2qp arithmetic;
// determines boundary membership (rel_err).
__device__ __forceinline__ float dist2(float4 q, float4 p) {
    float dot = __fadd_rn(__fadd_rn(__fmul_rn(q.x, p.x), __fmul_rn(q.y, p.y)),
                          __fmul_rn(q.z, p.z));
    return __fsub_rn(__fadd_rn(q.w, p.w), __fmul_rn(2.0f, dot));
}

// extract set bits of mask into lanes [found..K_) as neighbor indices
__device__ __forceinline__ void extract(unsigned mask, int base, int lane,
                                        int& found, int& my_idx) {
    while (mask && found < K_) {
        int bit = __ffs(mask) - 1;
        if (lane == found) my_idx = base + bit;
        mask &= mask - 1;
        found++;
    }
}

// single-query scan (fallback path for cross-batch pairs)
__device__ __forceinline__ int scan_one(const float4* __restrict__ pts, float4 q,
                                        int lane, int& found) {
    const unsigned FULL = 0xffffffffu;
    found = 0;
    int my_idx = 0;
    for (int base = 0; base < N_; base += 256) {
        float4 p0 = pts[base        + lane];
        float4 p1 = pts[base +  32 + lane];
        float4 p2 = pts[base +  64 + lane];
        float4 p3 = pts[base +  96 + lane];
        float4 p4 = pts[base + 128 + lane];
        float4 p5 = pts[base + 160 + lane];
        float4 p6 = pts[base + 192 + lane];
        float4 p7 = pts[base + 224 + lane];
        unsigned m0 = __ballot_sync(FULL, dist2(q, p0) <= R2);
        unsigned m1 = __ballot_sync(FULL, dist2(q, p1) <= R2);
        unsigned m2 = __ballot_sync(FULL, dist2(q, p2) <= R2);
        unsigned m3 = __ballot_sync(FULL, dist2(q, p3) <= R2);
        unsigned m4 = __ballot_sync(FULL, dist2(q, p4) <= R2);
        unsigned m5 = __ballot_sync(FULL, dist2(q, p5) <= R2);
        unsigned m6 = __ballot_sync(FULL, dist2(q, p6) <= R2);
        unsigned m7 = __ballot_sync(FULL, dist2(q, p7) <= R2);
        extract(m0, base,       lane, found, my_idx);
        extract(m1, base +  32, lane, found, my_idx);
        extract(m2, base +  64, lane, found, my_idx);
        extract(m3, base +  96, lane, found, my_idx);
        extract(m4, base + 128, lane, found, my_idx);
        extract(m5, base + 160, lane, found, my_idx);
        extract(m6, base + 192, lane, found, my_idx);
        extract(m7, base + 224, lane, found, my_idx);
        if (found >= K_) break;
    }
    return my_idx;
}

// MLP + maxpool for one query; lane j owns output channel j
__device__ __forceinline__ float mlp_one(const float4* __restrict__ pts,
                                         const float* __restrict__ featb,
                                         float4 q, int my_idx, int lane,
                                         const float* w1r, const float* w2r,
                                         float b1r, float b2r) {
    const unsigned FULL = 0xffffffffu;
    float acc = -3.402823466e38f;
    #pragma unroll 1
    for (int k = 0; k < K_; k++) {
        int g = __shfl_sync(FULL, my_idx, k);
        float4 p = pts[g];
        float f0 = featb[3 * g + 0];
        float f1 = featb[3 * g + 1];
        float f2 = featb[3 * g + 2];
        float i0 = p.x - q.x, i1 = p.y - q.y, i2 = p.z - q.z;

        float h1 = b1r;
        h1 += i0 * w1r[0];
        h1 += i1 * w1r[1];
        h1 += i2 * w1r[2];
        h1 += f0 * w1r[3];
        h1 += f1 * w1r[4];
        h1 += f2 * w1r[5];
        h1 = fmaxf(h1, 0.1f * h1);

        // 4 accumulator chains to break the serial FMA dependency
        float a0 = b2r, a1 = 0.f, a2 = 0.f, a3 = 0.f;
        #pragma unroll
        for (int i = 0; i < 32; i += 4) {
            a0 = fmaf(__shfl_sync(FULL, h1, i + 0), w2r[i + 0], a0);
            a1 = fmaf(__shfl_sync(FULL, h1, i + 1), w2r[i + 1], a1);
            a2 = fmaf(__shfl_sync(FULL, h1, i + 2), w2r[i + 2], a2);
            a3 = fmaf(__shfl_sync(FULL, h1, i + 3), w2r[i + 3], a3);
        }
        float h2 = (a0 + a1) + (a2 + a3);
        h2 = fmaxf(h2, 0.1f * h2);
        acc = fmaxf(acc, h2);
    }
    return acc;
}

__global__ __launch_bounds__(256) void sa_kernel(
    const float* __restrict__ feat,
    const int*   __restrict__ fps_idx,
    const float* __restrict__ W1,
    const float* __restrict__ b1,
    const float* __restrict__ W2,
    const float* __restrict__ b2,
    float*       __restrict__ out)
{
    const unsigned FULL = 0xffffffffu;
    int lane = threadIdx.x & 31;

    float w1r[6], w2r[32];
    #pragma unroll
    for (int i = 0; i < 6; i++)  w1r[i] = W1[i * 32 + lane];
    #pragma unroll
    for (int i = 0; i < 32; i++) w2r[i] = W2[i * 32 + lane];
    float b1r = b1[lane];
    float b2r = b2[lane];

    for (;;) {
        int idx;
        if (lane == 0) idx = (int)atomicAdd(&g_qctr, 2u);
        idx = __shfl_sync(FULL, idx, 0);
        if (idx >= NQ) break;
        int qidA = g_order[idx];
        int qidB = g_order[idx + 1];    // NQ even, idx even -> always valid

        int bA = qidA >> 12, bB = qidB >> 12;
        const float4* __restrict__ ptsA = g_pts + (size_t)bA * N_;
        const float4* __restrict__ ptsB = g_pts + (size_t)bB * N_;

        float4 qA = ptsA[fps_idx[qidA]];
        float4 qB = ptsB[fps_idx[qidB]];

        int foundA, foundB;
        int myA, myB;

        if (bA == bB) {
            // fused scan: each point load serves both queries
            foundA = 0; foundB = 0; myA = 0; myB = 0;
            for (int base = 0; base < N_; base += 128) {
                float4 p0 = ptsA[base       + lane];
                float4 p1 = ptsA[base +  32 + lane];
                float4 p2 = ptsA[base +  64 + lane];
                float4 p3 = ptsA[base +  96 + lane];
                unsigned a0 = __ballot_sync(FULL, dist2(qA, p0) <= R2);
                unsigned b0 = __ballot_sync(FULL, dist2(qB, p0) <= R2);
                unsigned a1 = __ballot_sync(FULL, dist2(qA, p1) <= R2);
                unsigned b1m = __ballot_sync(FULL, dist2(qB, p1) <= R2);
                unsigned a2 = __ballot_sync(FULL, dist2(qA, p2) <= R2);
                unsigned b2m = __ballot_sync(FULL, dist2(qB, p2) <= R2);
                unsigned a3 = __ballot_sync(FULL, dist2(qA, p3) <= R2);
                unsigned b3m = __ballot_sync(FULL, dist2(qB, p3) <= R2);
                if (foundA < K_) {
                    extract(a0, base,      lane, foundA, myA);
                    extract(a1, base + 32, lane, foundA, myA);
                    extract(a2, base + 64, lane, foundA, myA);
                    extract(a3, base + 96, lane, foundA, myA);
                }
                if (foundB < K_) {
                    extract(b0,  base,      lane, foundB, myB);
                    extract(b1m, base + 32, lane, foundB, myB);
                    extract(b2m, base + 64, lane, foundB, myB);
                    extract(b3m, base + 96, lane, foundB, myB);
                }
                if (foundA >= K_ && foundB >= K_) break;
            }
        } else {
            myA = scan_one(ptsA, qA, lane, foundA);
            myB = scan_one(ptsB, qB, lane, foundB);
        }

        // pad with first valid neighbor (always exists: query is in its ball)
        int firstA = __shfl_sync(FULL, myA, 0);
        if (lane >= foundA) myA = firstA;
        int firstB = __shfl_sync(FULL, myB, 0);
        if (lane >= foundB) myB = firstB;

        const float* __restrict__ featA = feat + (size_t)bA * N_ * 3;
        const float* __restrict__ featB = feat + (size_t)bB * N_ * 3;
        float accA = mlp_one(ptsA, featA, qA, myA, lane, w1r, w2r, b1r, b2r);
        float accB = mlp_one(ptsB, featB, qB, myB, lane, w1r, w2r, b1r, b2r);

        out[((size_t)qidA) * 32 + lane] = accA;
        out[((size_t)qidB) * 32 + lane] = accB;
    }
}

extern "C" void kernel_launch(void* const* d_in, const int* in_sizes, int n_in,
                              void* d_out, int out_size) {
    const float* xyz     = (const float*)d_in[0];
    const float* feat    = (const float*)d_in[1];
    const int*   fps_idx = (const int*)  d_in[2];
    const float* W1      = (const float*)d_in[3];
    const float* b1      = (const float*)d_in[4];
    const float* W2      = (const float*)d_in[5];
    const float* b2      = (const float*)d_in[6];
    float* out = (float*)d_out;

    prep_kernel<<<(B_ * N_ + 255) / 256, 256>>>(xyz);
    key_kernel<<<NQ / 256, 256>>>(fps_idx);
    prefix_kernel<<<1, B_ * BINS>>>();
    scatter_kernel<<<NQ / 256, 256>>>();
    sa_kernel<<<592, 256>>>(feat, fps_idx, W1, b1, W2, b2, out);
    (void)in_sizes; (void)n_in; (void)out_size;
}

// round 6
// speedup vs baseline: 1.2300x; 1.2300x over previous
#include <cuda_runtime.h>

#define B_  4
#define N_  16384
#define M_  4096
#define K_  16
#define R2  0.25f
#define NQ  (B_ * M_)

// Scratch: (x, y, z, |p|^2) per point. 4*16384*16B = 1 MB.
__device__ float4       g_pts[B_ * N_];
__device__ unsigned int g_qctr;   // work-stealing queue head

__global__ __launch_bounds__(256) void prep_kernel(const float* __restrict__ xyz) {
    int i = blockIdx.x * blockDim.x + threadIdx.x;
    if (i == 0) g_qctr = 0;       // reset queue every launch (graph replay safe)
    if (i < B_ * N_) {
        float x = xyz[3 * i + 0];
        float y = xyz[3 * i + 1];
        float z = xyz[3 * i + 2];
        // match jnp.sum(x**2,-1): (x*x + y*y) + z*z, no fma contraction
        float sq = __fadd_rn(__fadd_rn(__fmul_rn(x, x), __fmul_rn(y, y)), __fmul_rn(z, z));
        g_pts[i] = make_float4(x, y, z, sq);
    }
}

// DO NOT change: reproduces reference's expanded |q|^2+|p|^2-2qp arithmetic;
// determines boundary membership (rel_err).
__device__ __forceinline__ float dist2(float4 q, float4 p) {
    float dot = __fadd_rn(__fadd_rn(__fmul_rn(q.x, p.x), __fmul_rn(q.y, p.y)),
                          __fmul_rn(q.z, p.z));
    return __fsub_rn(__fadd_rn(q.w, p.w), __fmul_rn(2.0f, dot));
}

// take up to (K_ - found) lowest set bits of mask, in ascending order;
// lane r (r = lane - found) claims the (r+1)-th set bit. Warp-parallel.
__device__ __forceinline__ void extract_fns(unsigned mask, int base, int lane,
                                            int& found, int& my_idx) {
    int c = __popc(mask);
    if (c) {
        int take = K_ - found;
        if (take > c) take = c;
        int r = lane - found;
        if (r >= 0 && r < take) {
            my_idx = base + __fns(mask, 0, r + 1);
        }
        found += take;
    }
}

__global__ __launch_bounds__(256, 4) void sa_kernel(
    const float* __restrict__ feat,
    const int*   __restrict__ fps_idx,
    const float* __restrict__ W1,
    const float* __restrict__ b1,
    const float* __restrict__ W2,
    const float* __restrict__ b2,
    float*       __restrict__ out)
{
    const unsigned FULL = 0xffffffffu;
    int lane = threadIdx.x & 31;

    // hoist this lane's weight columns into registers (inner loops become
    // pure SHFL+FFMA, no LDS/LDG)
    float w1r[6], w2r[32];
    #pragma unroll
    for (int i = 0; i < 6; i++)  w1r[i] = W1[i * 32 + lane];
    #pragma unroll
    for (int i = 0; i < 32; i++) w2r[i] = W2[i * 32 + lane];
    float b1r = b1[lane];
    float b2r = b2[lane];

    // persistent warp: steal one query at a time
    for (;;) {
        int qid;
        if (lane == 0) qid = (int)atomicAdd(&g_qctr, 1u);
        qid = __shfl_sync(FULL, qid, 0);
        if (qid >= NQ) break;

        int b = qid >> 12;            // / M_ (4096)

        const float4* __restrict__ pts = g_pts + (size_t)b * N_;

        int    qi = fps_idx[qid];
        float4 q  = pts[qi];

        // ---- ball query: first K_ in-ball indices in ascending order ----
        // 8 independent 16B loads (256 points) in flight before the exit check.
        int found  = 0;
        int my_idx = 0;               // lane k (k<K_) owns neighbor k
        for (int base = 0; base < N_; base += 256) {
            float4 p0 = pts[base        + lane];
            float4 p1 = pts[base +  32 + lane];
            float4 p2 = pts[base +  64 + lane];
            float4 p3 = pts[base +  96 + lane];
            float4 p4 = pts[base + 128 + lane];
            float4 p5 = pts[base + 160 + lane];
            float4 p6 = pts[base + 192 + lane];
            float4 p7 = pts[base + 224 + lane];
            unsigned m0 = __ballot_sync(FULL, dist2(q, p0) <= R2);
            unsigned m1 = __ballot_sync(FULL, dist2(q, p1) <= R2);
            unsigned m2 = __ballot_sync(FULL, dist2(q, p2) <= R2);
            unsigned m3 = __ballot_sync(FULL, dist2(q, p3) <= R2);
            unsigned m4 = __ballot_sync(FULL, dist2(q, p4) <= R2);
            unsigned m5 = __ballot_sync(FULL, dist2(q, p5) <= R2);
            unsigned m6 = __ballot_sync(FULL, dist2(q, p6) <= R2);
            unsigned m7 = __ballot_sync(FULL, dist2(q, p7) <= R2);
            extract_fns(m0, base,       lane, found, my_idx);
            extract_fns(m1, base +  32, lane, found, my_idx);
            extract_fns(m2, base +  64, lane, found, my_idx);
            extract_fns(m3, base +  96, lane, found, my_idx);
            extract_fns(m4, base + 128, lane, found, my_idx);
            extract_fns(m5, base + 160, lane, found, my_idx);
            extract_fns(m6, base + 192, lane, found, my_idx);
            extract_fns(m7, base + 224, lane, found, my_idx);
            if (found >= K_) break;
        }
        // pad missing neighbors with the first valid one (reference semantics).
        // found >= 1 always: the query point is inside its own ball (d2 == 0).
        int idx0 = __shfl_sync(FULL, my_idx, 0);
        if (lane >= found) my_idx = idx0;
        int kmax = found < K_ ? found : K_;   // padded dups can't change the max

        // ---- MLP + maxpool: lane j owns output channel j ----
        const float* __restrict__ featb = feat + (size_t)b * N_ * 3;
        float acc = -3.402823466e38f;

        #pragma unroll 1
        for (int k = 0; k < kmax; k++) {
            int g = __shfl_sync(FULL, my_idx, k);
            float4 p = pts[g];                    // broadcast load (L1/L2 hit)
            float f0 = featb[3 * g + 0];
            float f1 = featb[3 * g + 1];
            float f2 = featb[3 * g + 2];
            float i0 = p.x - q.x, i1 = p.y - q.y, i2 = p.z - q.z;

            float h1 = b1r;
            h1 += i0 * w1r[0];
            h1 += i1 * w1r[1];
            h1 += i2 * w1r[2];
            h1 += f0 * w1r[3];
            h1 += f1 * w1r[4];
            h1 += f2 * w1r[5];
            h1 = fmaxf(h1, 0.1f * h1);            // leaky relu

            // 4 accumulator chains to break the serial FMA dependency
            float a0 = b2r, a1 = 0.f, a2 = 0.f, a3 = 0.f;
            #pragma unroll
            for (int i = 0; i < 32; i += 4) {
                a0 = fmaf(__shfl_sync(FULL, h1, i + 0), w2r[i + 0], a0);
                a1 = fmaf(__shfl_sync(FULL, h1, i + 1), w2r[i + 1], a1);
                a2 = fmaf(__shfl_sync(FULL, h1, i + 2), w2r[i + 2], a2);
                a3 = fmaf(__shfl_sync(FULL, h1, i + 3), w2r[i + 3], a3);
            }
            float h2 = (a0 + a1) + (a2 + a3);
            h2 = fmaxf(h2, 0.1f * h2);

            acc = fmaxf(acc, h2);
        }

        out[((size_t)qid) * 32 + lane] = acc;
    }
}

extern "C" void kernel_launch(void* const* d_in, const int* in_sizes, int n_in,
                              void* d_out, int out_size) {
    const float* xyz     = (const float*)d_in[0];
    const float* feat    = (const float*)d_in[1];
    const int*   fps_idx = (const int*)  d_in[2];
    const float* W1      = (const float*)d_in[3];
    const float* b1      = (const float*)d_in[4];
    const float* W2      = (const float*)d_in[5];
    const float* b2      = (const float*)d_in[6];
    float* out = (float*)d_out;

    prep_kernel<<<(B_ * N_ + 255) / 256, 256>>>(xyz);
    // persistent kernel: 4 CTAs/SM, work-stealing queue
    sa_kernel<<<592, 256>>>(feat, fps_idx, W1, b1, W2, b2, out);
    (void)in_sizes; (void)n_in; (void)out_size;
}